// round 2
// baseline (speedup 1.0000x reference)
#include <cuda_runtime.h>

// SpatialTransformer 3D trilinear resample.
// B=4, H=W=D=128, C=2, fp32. Output (B, H, W, D, C) fp32.
//
// Reference conventions reproduced exactly:
//  - meshgrid 'xy': grid flat index n = i*(W*D) + j*D + k with
//      x_g = linspace(-1,1,W)[j], y_g = linspace(-1,1,H)[i], z_g = linspace(-1,1,D)[k]
//  - pixel coords: p = 0.5*(v+1)*extent  (full extent)
//  - corner idx: floor, +1, then clip to [0, extent-1]; floats taken AFTER clip
//  - flat gather index: base + y*W + z*(W*H) + x   (reference's own convention)
//  - z-weights: near slab uses (z1f - z), far slab uses (z1f - z0f)

#define B_ 4
#define HH 128
#define WW 128
#define DD 128
#define NPB (HH * WW * DD)          // 2097152 points per batch
#define TOTAL (B_ * NPB)            // 8388608 threads

__global__ __launch_bounds__(256) void st3d_kernel(
    const float* __restrict__ image,   // [B, H, W, D, C] as flat, C=2
    const float* __restrict__ theta,   // [B, 3, 4]
    float2* __restrict__ out)          // [B*N] of float2 (C=2)
{
    const int tid = blockIdx.x * blockDim.x + threadIdx.x;
    if (tid >= TOTAL) return;

    const int b = tid >> 21;            // / NPB
    const int n = tid & (NPB - 1);
    const int k = n & 127;              // z (fastest)
    const int j = (n >> 7) & 127;       // x
    const int i = n >> 14;              // y

    const float s = 2.0f / 127.0f;
    const float xg = fmaf((float)j, s, -1.0f);
    const float yg = fmaf((float)i, s, -1.0f);
    const float zg = fmaf((float)k, s, -1.0f);

    const float* t = theta + b * 12;
    const float t0  = __ldg(t + 0),  t1  = __ldg(t + 1),  t2  = __ldg(t + 2),  t3  = __ldg(t + 3);
    const float t4  = __ldg(t + 4),  t5  = __ldg(t + 5),  t6  = __ldg(t + 6),  t7  = __ldg(t + 7);
    const float t8  = __ldg(t + 8),  t9  = __ldg(t + 9),  t10 = __ldg(t + 10), t11 = __ldg(t + 11);

    const float xo = fmaf(t0, xg, fmaf(t1, yg, fmaf(t2, zg, t3)));
    const float yo = fmaf(t4, xg, fmaf(t5, yg, fmaf(t6, zg, t7)));
    const float zo = fmaf(t8, xg, fmaf(t9, yg, fmaf(t10, zg, t11)));

    // map [-1,1] -> [0, extent] (full extent)
    const float px = (xo + 1.0f) * 64.0f;
    const float py = (yo + 1.0f) * 64.0f;
    const float pz = (zo + 1.0f) * 64.0f;

    const int fx = (int)floorf(px);
    const int fy = (int)floorf(py);
    const int fz = (int)floorf(pz);

    const int x0 = min(max(fx,     0), WW - 1);
    const int x1 = min(max(fx + 1, 0), WW - 1);
    const int y0 = min(max(fy,     0), HH - 1);
    const int y1 = min(max(fy + 1, 0), HH - 1);
    const int z0 = min(max(fz,     0), DD - 1);
    const int z1 = min(max(fz + 1, 0), DD - 1);

    const float x0f = (float)x0, x1f = (float)x1;
    const float y0f = (float)y0, y1f = (float)y1;
    const float z0f = (float)z0, z1f = (float)z1;

    const int base = b * NPB;
    // reference flat convention: base + y*W + z*(W*H) + x
    const int p00 = base + y0 * WW + z0 * (WW * HH);
    const int p10 = base + y1 * WW + z0 * (WW * HH);
    const int p01 = base + y0 * WW + z1 * (WW * HH);
    const int p11 = base + y1 * WW + z1 * (WW * HH);

    const float2* __restrict__ im2 = (const float2*)image;
    const float2 pa = __ldg(im2 + p00 + x0);
    const float2 pc = __ldg(im2 + p00 + x1);
    const float2 pb = __ldg(im2 + p10 + x0);
    const float2 pd = __ldg(im2 + p10 + x1);
    const float2 pe = __ldg(im2 + p01 + x0);
    const float2 pg = __ldg(im2 + p01 + x1);
    const float2 pf = __ldg(im2 + p11 + x0);
    const float2 ph = __ldg(im2 + p11 + x1);

    const float wx1 = x1f - px, wx0 = px - x0f;
    const float wy1 = y1f - py, wy0 = py - y0f;
    const float wzA = z1f - pz;          // near slab weight (z1f - z)
    const float wzB = z1f - z0f;         // far slab weight  (z1f - z0f) — ref convention

    float2 r;
    r.x = wzA * (wy1 * fmaf(wx1, pa.x, wx0 * pc.x) + wy0 * fmaf(wx1, pb.x, wx0 * pd.x))
        + wzB * (wy1 * fmaf(wx1, pe.x, wx0 * pg.x) + wy0 * fmaf(wx1, pf.x, wx0 * ph.x));
    r.y = wzA * (wy1 * fmaf(wx1, pa.y, wx0 * pc.y) + wy0 * fmaf(wx1, pb.y, wx0 * pd.y))
        + wzB * (wy1 * fmaf(wx1, pe.y, wx0 * pg.y) + wy0 * fmaf(wx1, pf.y, wx0 * ph.y));

    out[tid] = r;
}

extern "C" void kernel_launch(void* const* d_in, const int* in_sizes, int n_in,
                              void* d_out, int out_size) {
    const float* image = (const float*)d_in[0];
    const float* theta = (const float*)d_in[1];
    float2* out = (float2*)d_out;

    const int threads = 256;
    const int blocks = TOTAL / threads;  // 32768
    st3d_kernel<<<blocks, threads>>>(image, theta, out);
}

// round 3
// speedup vs baseline: 2.3721x; 2.3721x over previous
#include <cuda_runtime.h>

// SpatialTransformer 3D trilinear resample. B=4, H=W=D=128, C=2, fp32.
//
// R3: tile-transposed mapping.
//  - Compute phase: lane varies j (x) -> gather index (y*W + z*W*H + x) is
//    near-coalesced in x (affine is near-identity), ~3-4 lines per corner LDG
//    instead of 32.
//  - Results staged in a 32x32 float2 smem tile (row stride 33 -> conflict-free
//    for 8B accesses in both phases).
//  - Store phase: lane varies k -> fully coalesced 256B warp stores.
//
// Reference conventions reproduced exactly (see R0 notes): full-extent pixel
// mapping, clip-then-float corners, flat index base + y*W + z*W*H + x, and the
// (z1f - z0f) far-slab weight.

#define B_ 4
#define HH 128
#define WW 128
#define DD 128
#define NPB (HH * WW * DD)      // 2097152

__global__ __launch_bounds__(256) void st3d_kernel(
    const float* __restrict__ image,   // [B, H, W, D, C] flat, C=2
    const float* __restrict__ theta,   // [B, 3, 4]
    float2* __restrict__ out)          // [B*N] float2
{
    __shared__ float2 tile[32][33];    // [j_local][k_local], stride 33 kills conflicts

    const int tid  = threadIdx.x;
    const int lane = tid & 31;
    const int wid  = tid >> 5;

    // grid: 4 k-tiles * 4 j-tiles * 128 i * 4 b = 8192 blocks
    const unsigned bx = blockIdx.x;
    const int k0 = (bx & 3) << 5;
    const int j0 = ((bx >> 2) & 3) << 5;
    const int i  = (bx >> 4) & 127;
    const int b  = bx >> 11;

    const float* t = theta + b * 12;
    const float t0  = __ldg(t + 0),  t1  = __ldg(t + 1),  t2  = __ldg(t + 2),  t3  = __ldg(t + 3);
    const float t4  = __ldg(t + 4),  t5  = __ldg(t + 5),  t6  = __ldg(t + 6),  t7  = __ldg(t + 7);
    const float t8  = __ldg(t + 8),  t9  = __ldg(t + 9),  t10 = __ldg(t + 10), t11 = __ldg(t + 11);

    const float s = 2.0f / 127.0f;
    const int j = j0 + lane;                       // lane varies x
    const float xg = fmaf((float)j, s, -1.0f);
    const float yg = fmaf((float)i, s, -1.0f);

    // hoist the (xg, yg)-dependent part of the affine; only zg varies per iter
    const float cx = fmaf(t0, xg, fmaf(t1, yg, t3));
    const float cy = fmaf(t4, xg, fmaf(t5, yg, t7));
    const float cz = fmaf(t8, xg, fmaf(t9, yg, t11));

    const float2* __restrict__ im2 = (const float2*)image + (size_t)b * NPB;

    #pragma unroll
    for (int it = 0; it < 4; it++) {
        const int kl = wid + 8 * it;               // k_local 0..31, fixed per warp
        const float zg = fmaf((float)(k0 + kl), s, -1.0f);

        const float px = (fmaf(t2,  zg, cx) + 1.0f) * 64.0f;
        const float py = (fmaf(t6,  zg, cy) + 1.0f) * 64.0f;
        const float pz = (fmaf(t10, zg, cz) + 1.0f) * 64.0f;

        const int fx = (int)floorf(px);
        const int fy = (int)floorf(py);
        const int fz = (int)floorf(pz);

        const int x0 = min(max(fx,     0), WW - 1);
        const int x1 = min(max(fx + 1, 0), WW - 1);
        const int y0 = min(max(fy,     0), HH - 1);
        const int y1 = min(max(fy + 1, 0), HH - 1);
        const int z0 = min(max(fz,     0), DD - 1);
        const int z1 = min(max(fz + 1, 0), DD - 1);

        const float x0f = (float)x0, x1f = (float)x1;
        const float y0f = (float)y0, y1f = (float)y1;
        const float z0f = (float)z0, z1f = (float)z1;

        // reference flat convention: y*W + z*(W*H) + x (base folded into im2)
        const int p00 = y0 * WW + z0 * (WW * HH);
        const int p10 = y1 * WW + z0 * (WW * HH);
        const int p01 = y0 * WW + z1 * (WW * HH);
        const int p11 = y1 * WW + z1 * (WW * HH);

        const float2 pa = __ldg(im2 + p00 + x0);
        const float2 pc = __ldg(im2 + p00 + x1);
        const float2 pb = __ldg(im2 + p10 + x0);
        const float2 pd = __ldg(im2 + p10 + x1);
        const float2 pe = __ldg(im2 + p01 + x0);
        const float2 pg = __ldg(im2 + p01 + x1);
        const float2 pf = __ldg(im2 + p11 + x0);
        const float2 ph = __ldg(im2 + p11 + x1);

        const float wx1 = x1f - px, wx0 = px - x0f;
        const float wy1 = y1f - py, wy0 = py - y0f;
        const float wzA = z1f - pz;                // near slab (z1f - z)
        const float wzB = z1f - z0f;               // far slab  (z1f - z0f) — ref convention

        float2 r;
        r.x = wzA * (wy1 * fmaf(wx1, pa.x, wx0 * pc.x) + wy0 * fmaf(wx1, pb.x, wx0 * pd.x))
            + wzB * (wy1 * fmaf(wx1, pe.x, wx0 * pg.x) + wy0 * fmaf(wx1, pf.x, wx0 * ph.x));
        r.y = wzA * (wy1 * fmaf(wx1, pa.y, wx0 * pc.y) + wy0 * fmaf(wx1, pb.y, wx0 * pd.y))
            + wzB * (wy1 * fmaf(wx1, pe.y, wx0 * pg.y) + wy0 * fmaf(wx1, pf.y, wx0 * ph.y));

        tile[lane][kl] = r;
    }

    __syncthreads();

    // store phase: lane varies k -> coalesced 256B warp stores
    float2* __restrict__ op = out + (size_t)b * NPB + i * (WW * DD) + j0 * DD + k0;
    #pragma unroll
    for (int it = 0; it < 4; it++) {
        const int jl = wid + 8 * it;
        op[jl * DD + lane] = tile[jl][lane];
    }
}

extern "C" void kernel_launch(void* const* d_in, const int* in_sizes, int n_in,
                              void* d_out, int out_size) {
    const float* image = (const float*)d_in[0];
    const float* theta = (const float*)d_in[1];
    float2* out = (float2*)d_out;

    st3d_kernel<<<8192, 256>>>(image, theta, out);
}

// round 4
// speedup vs baseline: 3.4397x; 1.4501x over previous
#include <cuda_runtime.h>

// SpatialTransformer 3D trilinear resample. B=4, H=W=D=128, C=2, fp32.
//
// R4: same tile-transposed mapping as R3 (lane varies j/x for near-coalesced
// gathers; smem tile transpose; lane varies k for coalesced stores), plus:
//  - software-pipelined iterations (2-deep): ~16 LDG.64 in flight
//  - __launch_bounds__(256, 4) -> 64-reg cap so payloads stay live
//  - delta-based corner offsets to trim integer work
//
// Reference conventions reproduced exactly: full-extent pixel mapping,
// clip-then-float corners (x1 = clip(fx+1) — NOT min(x0+1,..), matters when
// fx < -1), flat index y*W + z*W*H + x, far-slab weight (z1f - z0f).

#define HH 128
#define WW 128
#define DD 128
#define NPB (HH * WW * DD)      // 2097152

struct Stage {
    float2 pa, pb, pc, pd, pe, pf, pg, ph;
    float wx1, wx0, wy1, wy0, wzA, wzB;
    int kl;
};

__device__ __forceinline__ void stage_load(
    const float2* __restrict__ im2,
    float t2, float t6, float t10,
    float cx, float cy, float cz,
    int k0, int kl, Stage& sg)
{
    sg.kl = kl;
    const float s = 2.0f / 127.0f;
    const float zg = fmaf((float)(k0 + kl), s, -1.0f);

    const float px = (fmaf(t2,  zg, cx) + 1.0f) * 64.0f;
    const float py = (fmaf(t6,  zg, cy) + 1.0f) * 64.0f;
    const float pz = (fmaf(t10, zg, cz) + 1.0f) * 64.0f;

    const int fx = __float2int_rd(px);
    const int fy = __float2int_rd(py);
    const int fz = __float2int_rd(pz);

    const int x0 = min(max(fx,     0), WW - 1);
    const int x1 = min(max(fx + 1, 0), WW - 1);
    const int y0 = min(max(fy,     0), HH - 1);
    const int y1 = min(max(fy + 1, 0), HH - 1);
    const int z0 = min(max(fz,     0), DD - 1);
    const int z1 = min(max(fz + 1, 0), DD - 1);

    // reference flat convention: y*W + z*(W*H) + x
    const int p00 = y0 * WW + z0 * (WW * HH) + x0;
    const int dx  = x1 - x0;               // 0 or 1 (or -? no: clip keeps >=)
    const int dy  = (y1 - y0) * WW;
    const int dz  = (z1 - z0) * (WW * HH);

    const float2* a = im2 + p00;
    sg.pa = __ldg(a);
    sg.pc = __ldg(a + dx);
    sg.pb = __ldg(a + dy);
    sg.pd = __ldg(a + dy + dx);
    const float2* e = a + dz;
    sg.pe = __ldg(e);
    sg.pg = __ldg(e + dx);
    sg.pf = __ldg(e + dy);
    sg.ph = __ldg(e + dy + dx);

    const float x0f = (float)x0, x1f = (float)x1;
    const float y0f = (float)y0, y1f = (float)y1;
    const float z0f = (float)z0, z1f = (float)z1;

    sg.wx1 = x1f - px;  sg.wx0 = px - x0f;
    sg.wy1 = y1f - py;  sg.wy0 = py - y0f;
    sg.wzA = z1f - pz;                 // near slab (z1f - z)
    sg.wzB = z1f - z0f;                // far slab  (z1f - z0f) — ref convention
}

__device__ __forceinline__ float2 stage_math(const Stage& sg)
{
    float2 r;
    r.x = sg.wzA * (sg.wy1 * fmaf(sg.wx1, sg.pa.x, sg.wx0 * sg.pc.x)
                  + sg.wy0 * fmaf(sg.wx1, sg.pb.x, sg.wx0 * sg.pd.x))
        + sg.wzB * (sg.wy1 * fmaf(sg.wx1, sg.pe.x, sg.wx0 * sg.pg.x)
                  + sg.wy0 * fmaf(sg.wx1, sg.pf.x, sg.wx0 * sg.ph.x));
    r.y = sg.wzA * (sg.wy1 * fmaf(sg.wx1, sg.pa.y, sg.wx0 * sg.pc.y)
                  + sg.wy0 * fmaf(sg.wx1, sg.pb.y, sg.wx0 * sg.pd.y))
        + sg.wzB * (sg.wy1 * fmaf(sg.wx1, sg.pe.y, sg.wx0 * sg.pg.y)
                  + sg.wy0 * fmaf(sg.wx1, sg.pf.y, sg.wx0 * sg.ph.y));
    return r;
}

__global__ __launch_bounds__(256, 4) void st3d_kernel(
    const float* __restrict__ image,   // [B, H, W, D, C] flat, C=2
    const float* __restrict__ theta,   // [B, 3, 4]
    float2* __restrict__ out)          // [B*N] float2
{
    __shared__ float2 tile[32][33];

    const int tid  = threadIdx.x;
    const int lane = tid & 31;
    const int wid  = tid >> 5;

    // grid: 4 k-tiles * 4 j-tiles * 128 i * 4 b = 8192 blocks
    const unsigned bx = blockIdx.x;
    const int k0 = (bx & 3) << 5;
    const int j0 = ((bx >> 2) & 3) << 5;
    const int i  = (bx >> 4) & 127;
    const int b  = bx >> 11;

    const float* t = theta + b * 12;
    const float t0  = __ldg(t + 0),  t1  = __ldg(t + 1),  t2  = __ldg(t + 2),  t3  = __ldg(t + 3);
    const float t4  = __ldg(t + 4),  t5  = __ldg(t + 5),  t6  = __ldg(t + 6),  t7  = __ldg(t + 7);
    const float t8  = __ldg(t + 8),  t9  = __ldg(t + 9),  t10 = __ldg(t + 10), t11 = __ldg(t + 11);

    const float s = 2.0f / 127.0f;
    const int j = j0 + lane;                       // lane varies x
    const float xg = fmaf((float)j, s, -1.0f);
    const float yg = fmaf((float)i, s, -1.0f);

    const float cx = fmaf(t0, xg, fmaf(t1, yg, t3));
    const float cy = fmaf(t4, xg, fmaf(t5, yg, t7));
    const float cz = fmaf(t8, xg, fmaf(t9, yg, t11));

    const float2* __restrict__ im2 = (const float2*)image + (size_t)b * NPB;

    // 2-deep software pipeline over the 4 k-iterations (kl = wid + 8*it)
    Stage s0, s1;
    stage_load(im2, t2, t6, t10, cx, cy, cz, k0, wid,      s0);
    stage_load(im2, t2, t6, t10, cx, cy, cz, k0, wid + 8,  s1);

    tile[lane][s0.kl] = stage_math(s0);
    stage_load(im2, t2, t6, t10, cx, cy, cz, k0, wid + 16, s0);

    tile[lane][s1.kl] = stage_math(s1);
    stage_load(im2, t2, t6, t10, cx, cy, cz, k0, wid + 24, s1);

    tile[lane][s0.kl] = stage_math(s0);
    tile[lane][s1.kl] = stage_math(s1);

    __syncthreads();

    // store phase: lane varies k -> coalesced 256B warp stores
    float2* __restrict__ op = out + (size_t)b * NPB + i * (WW * DD) + j0 * DD + k0;
    #pragma unroll
    for (int it = 0; it < 4; it++) {
        const int jl = wid + 8 * it;
        op[jl * DD + lane] = tile[jl][lane];
    }
}

extern "C" void kernel_launch(void* const* d_in, const int* in_sizes, int n_in,
                              void* d_out, int out_size) {
    const float* image = (const float*)d_in[0];
    const float* theta = (const float*)d_in[1];
    float2* out = (float2*)d_out;

    st3d_kernel<<<8192, 256>>>(image, theta, out);
}